// round 17
// baseline (speedup 1.0000x reference)
#include <cuda_runtime.h>
#include <cuda_fp16.h>
#include <mma.h>
#include <math.h>

using namespace nvcuda;

#define NN    512
#define FF    128
#define HH    256
#define MM    256
#define DEGN  8
#define HISTN 10
#define OO    64
#define PPV   2
#define MAXS  (10*NN)     /* 5120 */
#define NLVL  6
#define BM    64
#define BN    64
#define BK    16
#define NCTA  512
#define TPB2  256
#define SHSZ  26688
#define NGRP  16
#define CAPV  160         /* max steps per node per level */

/* -------- persistent scratch (device globals) ----------------------------- */
__device__ float g_hist [NN*HISTN*HH];
__device__ __align__(16) __half g_XF  [NN*512];
__device__ __align__(16) __half g_CH  [((MAXS+7)/8)*512];
__device__ __align__(16) __half g_ns_h[((MAXS+7)/8)*HH];
__device__ __align__(16) __half g_BB  [512*512];   /* rows 0..255 = D, 256..511 = E=[A|Wm2] */
__device__ __align__(16) __half g_wm1h[HH*HH];
__device__ __align__(16) __half g_wr_h[HH*HH];
__device__ __align__(16) __half g_fm_h[NN*MM];
__device__ float g_bias [512];
__device__ int   g_node [MAXS];
__device__ int   g_count[NN];
__device__ int   g_vis  [NN];
__device__ int   g_perm [NN];
__device__ __align__(128) unsigned g_grpc[NGRP][32];
__device__ unsigned g_rootc;
__device__ unsigned g_gen;

/* -------- shared overlays -------------------------------------------------- */
struct ZgSh  { __half sA[2][BM][BK]; __half sB[2][BK][BN]; float sO[BM][BN];
               const __half* P1[BM]; const __half* P2[BM]; };
struct SeqSh { float hist[HISTN][HH]; float kq[2][HH]; float vals[HH];
               float spart[8*HH]; float logit[16]; float attn[16];
               int sidx[CAPV]; int scnt; };
struct GaSh  { float sA[16][65]; float sB[16][65]; };
struct EncSh { float sx[FF]; };
struct OutSh { float fin[HH]; float lg[PPV*OO]; };

/* ------------------------- sync helpers ---------------------------------- */
__device__ __forceinline__ unsigned ldg_acq(const unsigned* p) {
    unsigned v;
    asm volatile("ld.acquire.gpu.global.b32 %0, [%1];" : "=r"(v) : "l"(p) : "memory");
    return v;
}
__device__ __forceinline__ void stg_rel(unsigned* p, unsigned v) {
    asm volatile("st.release.gpu.global.b32 [%0], %1;" :: "l"(p), "r"(v) : "memory");
}
__device__ __forceinline__ void gbar(int cta, unsigned target) {
    __syncthreads();
    if (threadIdx.x == 0) {
        __threadfence();
        int grp = cta >> 5;
        if (atomicAdd(&g_grpc[grp][0], 1u) == 31u) {
            *(volatile unsigned*)&g_grpc[grp][0] = 0u;
            __threadfence();
            if (atomicAdd(&g_rootc, 1u) == (unsigned)(NGRP-1)) {
                *(volatile unsigned*)&g_rootc = 0u;
                stg_rel(&g_gen, target);
            }
        }
        while ((int)(ldg_acq(&g_gen) - target) < 0) {}
    }
    __syncthreads();
}

__device__ __forceinline__ void level_bounds(int S, int level, int* plo, int* phi)
{
    int lo = 0, hi = (S < MAXS) ? S : MAXS;
    for (int l = 0; l < level; ++l) {
        lo = hi;
        int h2 = S + 8*hi;
        hi = (h2 > MAXS) ? MAXS : h2;
    }
    *plo = lo; *phi = hi;
}

/* ------------------- gemmA tile: A=Wq@Wk^T / Wm2-pack / bias -------------- */
__device__ void gemmA_tile(char* SH, int t5,
                           const float* __restrict__ Wq, const float* __restrict__ Wk,
                           const float* __restrict__ Wm, const float* __restrict__ bq,
                           const float* __restrict__ bm, int t)
{
    const int bx = t5 >> 2, by = t5 & 3;
    __syncthreads();
    if (bx >= 4) {
        int k0 = (bx-4)*64, j0 = by*64;
        for (int i = t; i < 64*64; i += TPB2) {
            int k = k0 + (i >> 6), j = j0 + (i & 63);
            g_BB[(size_t)(256 + k)*512 + 256 + j] = __float2half(Wm[(size_t)(256 + k)*MM + j]);
        }
        if (bx == 4 && by == 0) {
            int w = t >> 5, l = t & 31;
            for (int r0 = 0; r0 < HH; r0 += 8) {
                int r = r0 + w;
                float p = 0.f;
                #pragma unroll
                for (int k = 0; k < 8; ++k) { int h = l + k*32; p += Wk[(size_t)r*HH + h]*bq[h]; }
                #pragma unroll
                for (int o = 16; o > 0; o >>= 1) p += __shfl_down_sync(0xffffffffu, p, o);
                if (l == 0) g_bias[r] = p;
            }
            g_bias[256 + t] = bm[t];
        }
        return;
    }
    GaSh* ga = (GaSh*)SH;
    const int i0 = bx*64, j0 = by*64;
    const int tx = t & 15, ty = t >> 4;
    float acc[4][4];
    #pragma unroll
    for (int a = 0; a < 4; ++a)
        #pragma unroll
        for (int b = 0; b < 4; ++b) acc[a][b] = 0.f;
    for (int kt = 0; kt < HH; kt += 16) {
        int lr = t >> 2, lh = (t & 3)*4;
        float4 va = *(const float4*)(Wq + (size_t)(i0+lr)*HH + kt + lh);
        ga->sA[lh+0][lr]=va.x; ga->sA[lh+1][lr]=va.y; ga->sA[lh+2][lr]=va.z; ga->sA[lh+3][lr]=va.w;
        float4 vb = *(const float4*)(Wk + (size_t)(j0+lr)*HH + kt + lh);
        ga->sB[lh+0][lr]=vb.x; ga->sB[lh+1][lr]=vb.y; ga->sB[lh+2][lr]=vb.z; ga->sB[lh+3][lr]=vb.w;
        __syncthreads();
        #pragma unroll
        for (int h = 0; h < 16; ++h) {
            float ra[4], rb[4];
            #pragma unroll
            for (int a = 0; a < 4; ++a) ra[a] = ga->sA[h][ty*4 + a];
            #pragma unroll
            for (int b = 0; b < 4; ++b) rb[b] = ga->sB[h][tx*4 + b];
            #pragma unroll
            for (int a = 0; a < 4; ++a)
                #pragma unroll
                for (int b = 0; b < 4; ++b) acc[a][b] += ra[a]*rb[b];
        }
        __syncthreads();
    }
    #pragma unroll
    for (int a = 0; a < 4; ++a)
        #pragma unroll
        for (int b = 0; b < 4; ++b)
            g_BB[(size_t)(256 + i0 + ty*4 + a)*512 + (j0 + tx*4 + b)] = __float2half(acc[a][b]);
}

/* ------------------- gemmD tile: D = Wm1 @ E (2-deep prefetch) ------------ */
__device__ void gemmD_tile(char* SH, int t5, int tid)
{
    ZgSh* z = (ZgSh*)SH;
    const int m0 = (t5 >> 3) * BM, n0 = (t5 & 7) * BN;
    const int wid = tid >> 5, wr = wid & 3, wc = wid >> 2;
    const int ar = tid >> 2, ac = (tid & 3)*4;
    const int brw = tid >> 4, bc = (tid & 15)*4;
    const int KT = HH / BK;
    __syncthreads();
    wmma::fragment<wmma::accumulator,16,16,16,float> acc[2];
    wmma::fill_fragment(acc[0], 0.f);
    wmma::fill_fragment(acc[1], 0.f);
    #define LDA_D(k) (*(const uint2*)(g_wm1h + (size_t)(m0+ar)*HH + (k)*BK + ac))
    #define LDB_D(k) (*(const uint2*)(g_BB + (size_t)(256 + (k)*BK + brw)*512 + n0 + bc))
    uint2 rA[2], rB[2];
    {
        uint2 tA = LDA_D(0), tB = LDB_D(0);
        *(uint2*)&z->sA[0][ar][ac] = tA;
        *(uint2*)&z->sB[0][brw][bc] = tB;
        rA[1] = LDA_D(1); rB[1] = LDB_D(1);
        rA[0] = LDA_D(2); rB[0] = LDB_D(2);
    }
    __syncthreads();
    for (int k = 0; k < KT; ++k) {
        const int p = k & 1, q = p ^ 1;
        if (k + 1 < KT) {
            *(uint2*)&z->sA[q][ar][ac] = rA[q];
            *(uint2*)&z->sB[q][brw][bc] = rB[q];
        }
        if (k + 3 < KT) { rA[q] = LDA_D(k+3); rB[q] = LDB_D(k+3); }
        wmma::fragment<wmma::matrix_a,16,16,16,__half,wmma::row_major> fa;
        wmma::load_matrix_sync(fa, &z->sA[p][wr*16][0], BK);
        #pragma unroll
        for (int j = 0; j < 2; ++j) {
            wmma::fragment<wmma::matrix_b,16,16,16,__half,wmma::row_major> fb;
            wmma::load_matrix_sync(fb, &z->sB[p][0][wc*32 + j*16], BN);
            wmma::mma_sync(acc[j], fa, fb, acc[j]);
        }
        __syncthreads();
    }
    #undef LDA_D
    #undef LDB_D
    wmma::store_matrix_sync(&z->sO[wr*16][wc*32],      acc[0], BN, wmma::mem_row_major);
    wmma::store_matrix_sync(&z->sO[wr*16][wc*32 + 16], acc[1], BN, wmma::mem_row_major);
    __syncthreads();
    for (int idx = tid; idx < BM*BN; idx += TPB2) {
        int r = idx >> 6, nl = idx & 63;
        g_BB[(size_t)(m0 + r)*512 + n0 + nl] = __float2half(z->sO[r][nl]);
    }
}

/* ------------------- zg tile: CH/XF = [NS|W2] @ BB + bias (2-deep) -------- */
__device__ void zg_tile(char* SH, int level, int S, int rlo, int rhi,
                        int m0, int n0, int tid)
{
    ZgSh* z = (ZgSh*)SH;
    __syncthreads();
    if (tid < BM) {
        int p = rlo + m0 + tid;
        if (p < rhi) {
            if (level < 0) {
                z->P1[tid] = 0;
                z->P2[tid] = g_fm_h + (size_t)p*MM;
            } else {
                z->P1[tid] = g_ns_h + (size_t)p*HH;
                z->P2[tid] = (p < S) ? (g_XF + (size_t)p*512 + 256)
                                     : (g_CH + (size_t)((p - S) >> 3)*512 + 256);
            }
        } else { z->P1[tid] = 0; z->P2[tid] = 0; }
    }
    __syncthreads();
    const int wid = tid >> 5, wr = wid & 3, wc = wid >> 2;
    const int ar = tid >> 2, ac = (tid & 3)*4;
    const int brw = tid >> 4, bc = (tid & 15)*4;
    const __half* p1 = z->P1[ar];
    const __half* p2 = z->P2[ar];
    wmma::fragment<wmma::accumulator,16,16,16,float> acc[2];
    wmma::fill_fragment(acc[0], 0.f);
    wmma::fill_fragment(acc[1], 0.f);
    const int KT = 512 / BK;
    #define LDA_Z(k) ({ int kt = (k)*BK; const __half* b_ = (kt < 256) ? p1 : p2; \
                        b_ ? *(const uint2*)(b_ + (kt & 255) + ac) : make_uint2(0u,0u); })
    #define LDB_Z(k) (*(const uint2*)(g_BB + (size_t)((k)*BK + brw)*512 + n0 + bc))
    uint2 rA[2], rB[2];
    {
        uint2 tA = LDA_Z(0), tB = LDB_Z(0);
        *(uint2*)&z->sA[0][ar][ac] = tA;
        *(uint2*)&z->sB[0][brw][bc] = tB;
        rA[1] = LDA_Z(1); rB[1] = LDB_Z(1);
        rA[0] = LDA_Z(2); rB[0] = LDB_Z(2);
    }
    __syncthreads();
    for (int k = 0; k < KT; ++k) {
        const int p = k & 1, q = p ^ 1;
        if (k + 1 < KT) {
            *(uint2*)&z->sA[q][ar][ac] = rA[q];
            *(uint2*)&z->sB[q][brw][bc] = rB[q];
        }
        if (k + 3 < KT) { rA[q] = LDA_Z(k+3); rB[q] = LDB_Z(k+3); }
        wmma::fragment<wmma::matrix_a,16,16,16,__half,wmma::row_major> fa;
        wmma::load_matrix_sync(fa, &z->sA[p][wr*16][0], BK);
        #pragma unroll
        for (int j = 0; j < 2; ++j) {
            wmma::fragment<wmma::matrix_b,16,16,16,__half,wmma::row_major> fb;
            wmma::load_matrix_sync(fb, &z->sB[p][0][wc*32 + j*16], BN);
            wmma::mma_sync(acc[j], fa, fb, acc[j]);
        }
        __syncthreads();
    }
    #undef LDA_Z
    #undef LDB_Z
    wmma::store_matrix_sync(&z->sO[wr*16][wc*32],      acc[0], BN, wmma::mem_row_major);
    wmma::store_matrix_sync(&z->sO[wr*16][wc*32 + 16], acc[1], BN, wmma::mem_row_major);
    __syncthreads();
    __half* outp = (level < 0) ? g_XF : g_CH;
    for (int idx = tid; idx < BM*BN; idx += TPB2) {
        int r = idx >> 6, nl = idx & 63;
        int pp = rlo + m0 + r;
        if (pp < rhi) {
            int n = n0 + nl;
            outp[(size_t)pp*512 + n] = __float2half(z->sO[r][nl] + g_bias[n]);
        }
    }
}

__device__ void zg_phase(char* SH, int level, int S, int rlo, int rhi, int tid, int cta)
{
    int rows = rhi - rlo, RT = (rows + BM - 1) / BM;
    for (int t5 = cta; t5 < RT*8; t5 += NCTA)
        zg_tile(SH, level, S, rlo, rhi, (t5 >> 3)*BM, (t5 & 7)*BN, tid);
}

/* ------- seq: per-node chain within level (direct range scan) ------------- */
__device__ void seq_phase(char* SH, int lo, int hi, int S,
                          const float* __restrict__ br, int tid, int nd)
{
    SeqSh* q = (SeqSh*)SH;
    const int PM = (MAXS - S + 7) >> 3;
    if (tid == 0) q->scnt = 0;
    __syncthreads();
    for (int j = lo + tid; j < hi; j += TPB2) {
        if (g_node[j] == nd) {
            int pos = atomicAdd(&q->scnt, 1);
            if (pos < CAPV) q->sidx[pos] = j;
        }
    }
    __syncthreads();
    int nsteps = q->scnt; if (nsteps > CAPV) nsteps = CAPV;
    if (nsteps == 0) return;
    if (tid == 0) {
        for (int i = 1; i < nsteps; ++i) {
            int v = q->sidx[i], j = i - 1;
            while (j >= 0 && q->sidx[j] > v) { q->sidx[j+1] = q->sidx[j]; --j; }
            q->sidx[j+1] = v;
        }
    }
    #pragma unroll
    for (int r = 0; r < HISTN; ++r)
        q->hist[r][tid] = g_hist[((size_t)nd*HISTN + r)*HH + tid];
    __syncthreads();
    int cnt = g_count[nd];
    const int wid = tid >> 5, lid = tid & 31;
    const float brv = br[tid];
    {
        int s0 = q->sidx[0];
        const __half* kqp = (s0 < S) ? (g_XF + (size_t)s0*512)
                                     : (g_CH + (size_t)((s0 - S) >> 3)*512);
        q->kq[0][tid] = __half2float(__ldg(kqp + tid));
    }
    __syncthreads();

    for (int i = 0; i < nsteps; ++i) {
        const int buf   = i & 1;
        const int sstep = q->sidx[i];
        float nkq = 0.f;
        const bool hn = (i + 1 < nsteps);
        if (hn) {
            int s2 = q->sidx[i+1];
            const __half* kqp = (s2 < S) ? (g_XF + (size_t)s2*512)
                                         : (g_CH + (size_t)((s2 - S) >> 3)*512);
            nkq = __half2float(__ldg(kqp + tid));
        }
        const int nv   = (cnt < HISTN) ? cnt : HISTN;
        const int slot = cnt % HISTN;
        const float* kq = q->kq[buf];
        #pragma unroll
        for (int pass = 0; pass < 2; ++pass) {
            int sl = wid + pass*8;
            if (sl < nv) {
                const float* hp = q->hist[sl];
                float p = 0.f;
                #pragma unroll
                for (int k = 0; k < 8; ++k) { int h = lid + k*32; p += hp[h]*kq[h]; }
                #pragma unroll
                for (int o = 16; o > 0; o >>= 1) p += __shfl_down_sync(0xffffffffu, p, o);
                if (lid == 0) q->logit[sl] = p * 0.0625f;
            }
        }
        __syncthreads();                               /* (1) logits */
        if (tid < 32) {
            float lg = (tid < nv) ? q->logit[tid] : -1e30f;
            float m = lg;
            #pragma unroll
            for (int o = 16; o > 0; o >>= 1) m = fmaxf(m, __shfl_xor_sync(0xffffffffu, m, o));
            float e = (tid < nv) ? __expf(lg - m) : 0.f;
            float s = e;
            #pragma unroll
            for (int o = 16; o > 0; o >>= 1) s += __shfl_xor_sync(0xffffffffu, s, o);
            if (tid < 16) q->attn[tid] = e / s;
        }
        __syncthreads();                               /* (2) attn */
        {   /* per-warp vals: warp w owns rows [32w,32w+32) */
            const int r = wid*32 + lid;
            float v = 0.f;
            #pragma unroll 2
            for (int k = 0; k < nv; ++k) v += q->attn[k]*q->hist[k][r];
            q->vals[r] = v;
            __syncwarp();
        }
        {   /* matvec: warp w uses ONLY its own rows (no CTA sync needed) */
            float a0=0,a1=0,a2=0,a3=0,a4=0,a5=0,a6=0,a7=0;
            const int r0 = wid*32;
            const float4* Wv = (const float4*)g_wr_h;
            #pragma unroll 8
            for (int r = r0; r < r0+32; ++r) {
                float x = q->vals[r];
                float4 w = __ldg(&Wv[(size_t)r*32 + lid]);
                const half2* hp = (const half2*)&w;
                float2 f0 = __half22float2(hp[0]);
                float2 f1 = __half22float2(hp[1]);
                float2 f2 = __half22float2(hp[2]);
                float2 f3 = __half22float2(hp[3]);
                a0 += x*f0.x; a1 += x*f0.y; a2 += x*f1.x; a3 += x*f1.y;
                a4 += x*f2.x; a5 += x*f2.y; a6 += x*f3.x; a7 += x*f3.y;
            }
            float4* sp4 = (float4*)q->spart;
            sp4[(size_t)wid*64 + lid*2 + 0] = make_float4(a0,a1,a2,a3);
            sp4[(size_t)wid*64 + lid*2 + 1] = make_float4(a4,a5,a6,a7);
        }
        if (hn) q->kq[buf ^ 1][tid] = nkq;
        __syncthreads();                               /* (3) partials + next kq */
        {
            float r = brv;
            #pragma unroll
            for (int k = 0; k < 8; ++k) r += q->spart[k*HH + tid];
            q->hist[slot][tid] = r;
            if (sstep < PM) g_ns_h[(size_t)sstep*HH + tid] = __float2half(r);
        }
        ++cnt;
        __syncthreads();                               /* (4) hist updated */
    }
    #pragma unroll
    for (int r = 0; r < HISTN; ++r)
        g_hist[((size_t)nd*HISTN + r)*HH + tid] = q->hist[r][tid];
    if (tid == 0) g_count[nd] = cnt;
}

/* ------------------- mega kernel ------------------------------------------ */
__global__ void __launch_bounds__(TPB2, 4)
k_mega(const float* __restrict__ xa, const int* __restrict__ nbr,
       const float* __restrict__ fm,
       const float* __restrict__ We, const float* __restrict__ be,
       const float* __restrict__ Wq, const float* __restrict__ bq,
       const float* __restrict__ Wk,
       const float* __restrict__ Wr, const float* __restrict__ br,
       const float* __restrict__ Wm, const float* __restrict__ bm,
       const float* __restrict__ Wd, const float* __restrict__ bd,
       const int* __restrict__ nS, float* __restrict__ out)
{
    __shared__ __align__(16) char SH[SHSZ];
    __shared__ unsigned sh_base;
    const int cta = blockIdx.x, tid = threadIdx.x;
    const int S = *nS;
    const int PM = (MAXS - S + 7) >> 3;

    if (tid == 0) sh_base = *(volatile unsigned*)&g_gen;
    __syncthreads();
    unsigned bt = sh_base;

    /* ---- B0: node init [0,S), vis init, encode, packs, gemmA ------------- */
    for (int e = cta*TPB2 + tid; e < S && e < MAXS; e += NCTA*TPB2) g_node[e] = e;
    {
        EncSh* es = (EncSh*)SH;
        const int n = cta;
        if (tid < FF) es->sx[tid] = xa[n*FF + tid];
        __syncthreads();
        float acc = be[tid];
        #pragma unroll 4
        for (int f = 0; f < FF; ++f) acc += es->sx[f] * We[f*HH + tid];
        g_hist[((size_t)n*HISTN + 0)*HH + tid] = acc;
        g_fm_h[(size_t)n*MM + tid] = __float2half(fm[(size_t)n*MM + tid]);
        if (tid == 0) { g_count[n] = 1; g_vis[n] = (n < S) ? 1 : 0; }
        __syncthreads();
    }
    if (cta < HH) {
        const int r = cta;
        g_wm1h[(size_t)r*MM + tid] = __float2half(Wm[(size_t)r*MM + tid]);
        float s = Wr[r*HH + tid] + Wr[(HH + r)*HH + tid]
                + Wr[(2*HH + r)*HH + tid] + Wr[(3*HH + r)*HH + tid];
        g_wr_h[r*HH + tid] = __float2half(s);
    }
    if (cta >= NCTA-32) gemmA_tile(SH, cta - (NCTA-32), Wq, Wk, Wm, bq, bm, tid);
    gbar(cta, ++bt);

    /* ---- expansion phases (fused: lvl1 += gemmD, lvl2 += XF seed) --------- */
    for (int lvl = 1; lvl < NLVL; ++lvl) {
        int lo, hi; level_bounds(S, lvl, &lo, &hi);
        if (lo >= hi) break;
        for (int e = lo + cta*TPB2 + tid; e < hi; e += NCTA*TPB2) {
            int src = (e - S) >> 3;
            int nd = nbr[g_node[src]*DEGN + ((e - S) & 7)];
            g_node[e] = nd;
            atomicAdd(&g_vis[nd], 1);
        }
        if (lvl == 1 && cta < 32) gemmD_tile(SH, cta, tid);
        if (lvl == 2) zg_phase(SH, -1, S, 0, (S < NN) ? S : NN, tid, cta);
        gbar(cta, ++bt);
    }

    /* ---- perm phase: counting-sort nodes by total visits (descending) ----- */
    if (cta == 0) {
        int* bins = (int*)SH;            /* CAPV+1 bins */
        for (int i = tid; i <= CAPV; i += TPB2) bins[i] = 0;
        __syncthreads();
        for (int n = tid; n < NN; n += TPB2) {
            int v = g_vis[n]; if (v > CAPV) v = CAPV;
            atomicAdd(&bins[CAPV - v], 1);
        }
        __syncthreads();
        if (tid == 0) {
            int run = 0;
            for (int b = 0; b <= CAPV; ++b) { int t = bins[b]; bins[b] = run; run += t; }
        }
        __syncthreads();
        for (int n = tid; n < NN; n += TPB2) {
            int v = g_vis[n]; if (v > CAPV) v = CAPV;
            int pos = atomicAdd(&bins[CAPV - v], 1);
            g_perm[pos] = n;
        }
    }
    gbar(cta, ++bt);
    const int mynode = g_perm[cta];

    /* ---- levels: seq -> zg ----------------------------------------------- */
    for (int lvl = 0; lvl < NLVL; ++lvl) {
        int lo, hi; level_bounds(S, lvl, &lo, &hi);
        if (lo >= hi) break;
        seq_phase(SH, lo, hi, S, br, tid, mynode);
        gbar(cta, ++bt);
        int rhi = (hi < PM) ? hi : PM;
        if (lo < rhi) {
            zg_phase(SH, lvl, S, lo, rhi, tid, cta);
            gbar(cta, ++bt);
        }
    }

    /* ---- out: decoder + log_softmax -------------------------------------- */
    {
        OutSh* o = (OutSh*)SH;
        int cnt  = g_count[cta];
        int slot = (cnt - 1) % HISTN;
        o->fin[tid] = g_hist[((size_t)cta*HISTN + slot)*HH + tid];
        __syncthreads();
        if (tid < PPV*OO) {
            int p = tid >> 6, qo = tid & 63;
            float acc = bd[p*OO + qo];
            #pragma unroll 4
            for (int h = 0; h < HH; ++h) acc += o->fin[h]*Wd[((size_t)p*HH + h)*OO + qo];
            o->lg[tid] = acc;
        }
        __syncthreads();
        if (tid < PPV*OO) {
            int p = tid >> 6, qo = tid & 63;
            float m = -1e30f;
            for (int k = 0; k < OO; ++k) m = fmaxf(m, o->lg[p*OO + k]);
            float sum = 0.f;
            for (int k = 0; k < OO; ++k) sum += expf(o->lg[p*OO + k] - m);
            out[((size_t)p*NN + cta)*OO + qo] = o->lg[tid] - m - logf(sum);
        }
    }
}

/* -------------------------------------------------------------------------- */
extern "C" void kernel_launch(void* const* d_in, const int* in_sizes, int n_in,
                              void* d_out, int out_size)
{
    const float* xa  = (const float*)d_in[0];
    const int*   nbr = (const int*)  d_in[1];
    const float* fm  = (const float*)d_in[2];
    const float* We  = (const float*)d_in[3];
    const float* be  = (const float*)d_in[4];
    const float* Wq  = (const float*)d_in[5];
    const float* bq  = (const float*)d_in[6];
    const float* Wk  = (const float*)d_in[7];
    /* d_in[8] = bk cancels in softmax */
    const float* Wr  = (const float*)d_in[9];
    const float* br  = (const float*)d_in[10];
    const float* Wm  = (const float*)d_in[11];
    const float* bm  = (const float*)d_in[12];
    const float* Wd  = (const float*)d_in[13];
    const float* bd  = (const float*)d_in[14];
    const int*   nS  = (const int*)  d_in[15];

    k_mega<<<NCTA, TPB2>>>(xa, nbr, fm, We, be, Wq, bq, Wk, Wr, br,
                           Wm, bm, Wd, bd, nS, (float*)d_out);
}